// round 6
// baseline (speedup 1.0000x reference)
#include <cuda_runtime.h>

#define S_ 8
#define U_ 32
#define V_ 32
#define C_ 32
#define SU 256              // S_*U_
#define SV 256              // S_*V_
#define WSEG (S_*U_*V_)     // 8192 floats per segment
#define WS_STRIDE 514       // u64 (float2) per s-slice: 512 + 2 pad -> bank offset 4s
#define NBLOCKS 296         // 2 per SM on 148 SMs

// Thread = (row, s). Warp = 4 rows x 8 s. W (premultiplied by coef) lives in
// padded SMEM, broadcast-read conflict-free; x and accumulators live in NAMED
// registers (no arrays -> no spill). One ulonglong2 of W live at a time.
__global__ __launch_bounds__(256, 2)
void idxlin_kernel(const float* __restrict__ W,     // (C, S*U*V)
                   const float* __restrict__ X,     // (Z, S*U)
                   const int*   __restrict__ counts,
                   const float* __restrict__ coef,
                   float* __restrict__ out,         // (Z, S*V)
                   int Z)
{
    __shared__ __align__(16) unsigned long long w_sh[S_ * WS_STRIDE]; // 32.9 KB
    __shared__ int segStart[C_ + 1];

    const int tid = threadIdx.x;
    if (tid == 0) {
        int a = 0; segStart[0] = 0;
        #pragma unroll
        for (int c = 0; c < C_; ++c) { a += counts[c]; segStart[c + 1] = a; }
    }
    __syncthreads();

    const int lane = tid & 31;
    const int wid  = tid >> 5;
    const int s    = lane & 7;   // 8 s per warp -> W-LDS banks tile fully
    const int r4   = lane >> 3;  // 4 rows per warp (broadcast groups)

    const int rpb = (Z + NBLOCKS - 1) / NBLOCKS;
    const int lo  = blockIdx.x * rpb;
    const int hi  = min(lo + rpb, Z);
    if (lo >= Z) return;   // uniform per block

    int seg = 0;
    while (seg < C_ - 1 && segStart[seg + 1] <= lo) seg++;

    int cur = lo;
    while (cur < hi) {
        const int segTop = (seg < C_ - 1) ? segStart[seg + 1] : Z;
        const int e = min(segTop, hi);

        // ---- stage premultiplied W[seg] into padded SMEM (coalesced) ----
        __syncthreads();   // previous readers done with w_sh
        {
            const float4* wg = reinterpret_cast<const float4*>(W + (size_t)seg * WSEG);
            #pragma unroll
            for (int k = 0; k < WSEG / 4 / 256; ++k) {      // 8 iters
                const int idx4 = tid + 256 * k;
                float4 w = wg[idx4];
                const int ss  = idx4 >> 8;     // 256 float4 per s-slice
                const int rem = idx4 & 255;
                const float c0 = coef[ss];
                w.x *= c0; w.y *= c0; w.z *= c0; w.w *= c0;
                *reinterpret_cast<float4*>(&w_sh[ss * WS_STRIDE + rem * 2]) = w;
            }
        }
        __syncthreads();

        const unsigned long long* wbase = &w_sh[s * WS_STRIDE];

        // ---- barrier-free row loop ----
        for (int r = cur + wid * 4 + r4; r < e; r += 32) {
            const float4* xg = reinterpret_cast<const float4*>(
                X + (size_t)r * SU + s * U_);
            float4 x0 = xg[0], x1 = xg[1], x2 = xg[2], x3 = xg[3];
            float4 x4 = xg[4], x5 = xg[5], x6 = xg[6], x7 = xg[7];

            unsigned long long A0=0,A1=0,A2=0,A3=0,A4=0,A5=0,A6=0,A7=0,
                               A8=0,A9=0,A10=0,A11=0,A12=0,A13=0,A14=0,A15=0;

#define FMA2(acc, xx, ww) \
    asm("fma.rn.f32x2 %0, %1, %2, %0;" : "+l"(acc) : "l"(xx), "l"(ww));
#define DO_U(xs, u) {                                                          \
    unsigned long long xx;                                                     \
    asm("mov.b64 %0, {%1, %1};" : "=l"(xx) : "f"(xs));                         \
    const ulonglong2* wr = reinterpret_cast<const ulonglong2*>(                \
        wbase + (u) * (V_ / 2));                                               \
    ulonglong2 ww;                                                             \
    ww = wr[0]; FMA2(A0,  xx, ww.x) FMA2(A1,  xx, ww.y)                        \
    ww = wr[1]; FMA2(A2,  xx, ww.x) FMA2(A3,  xx, ww.y)                        \
    ww = wr[2]; FMA2(A4,  xx, ww.x) FMA2(A5,  xx, ww.y)                        \
    ww = wr[3]; FMA2(A6,  xx, ww.x) FMA2(A7,  xx, ww.y)                        \
    ww = wr[4]; FMA2(A8,  xx, ww.x) FMA2(A9,  xx, ww.y)                        \
    ww = wr[5]; FMA2(A10, xx, ww.x) FMA2(A11, xx, ww.y)                        \
    ww = wr[6]; FMA2(A12, xx, ww.x) FMA2(A13, xx, ww.y)                        \
    ww = wr[7]; FMA2(A14, xx, ww.x) FMA2(A15, xx, ww.y)                        \
    }
#define DO_QUAD(xq, ub) DO_U((xq).x, ub) DO_U((xq).y, (ub)+1) \
                        DO_U((xq).z, (ub)+2) DO_U((xq).w, (ub)+3)

            DO_QUAD(x0,  0) DO_QUAD(x1,  4) DO_QUAD(x2,  8) DO_QUAD(x3, 12)
            DO_QUAD(x4, 16) DO_QUAD(x5, 20) DO_QUAD(x6, 24) DO_QUAD(x7, 28)
#undef DO_QUAD
#undef DO_U
#undef FMA2

            float4* og = reinterpret_cast<float4*>(out + (size_t)r * SV + s * V_);
            float2 pa, pb;
#define STORE4(k, Aa, Ab) \
    pa = *reinterpret_cast<float2*>(&Aa); pb = *reinterpret_cast<float2*>(&Ab); \
    og[k] = make_float4(pa.x, pa.y, pb.x, pb.y);
            STORE4(0, A0,  A1)  STORE4(1, A2,  A3)
            STORE4(2, A4,  A5)  STORE4(3, A6,  A7)
            STORE4(4, A8,  A9)  STORE4(5, A10, A11)
            STORE4(6, A12, A13) STORE4(7, A14, A15)
#undef STORE4
        }

        cur = e;
        seg++;
        if (seg >= C_ && cur < hi) break;  // safety if counts undersum
    }
}

extern "C" void kernel_launch(void* const* d_in, const int* in_sizes, int n_in,
                              void* d_out, int out_size) {
    const float* W      = (const float*)d_in[0];   // input1 (C, S*U*V)
    const float* X      = (const float*)d_in[1];   // input2 (Z, S*U)
    const int*   counts = (const int*)d_in[2];
    const float* coef   = (const float*)d_in[3];
    float* out = (float*)d_out;

    int Z = in_sizes[1] / SU;
    idxlin_kernel<<<NBLOCKS, 256>>>(W, X, counts, coef, out, Z);
}

// round 7
// speedup vs baseline: 4.6582x; 4.6582x over previous
#include <cuda_runtime.h>

#define S_ 8
#define U_ 32
#define V_ 32
#define C_ 32
#define SU 256              // S_*U_
#define SV 256              // S_*V_
#define WSEG (S_*U_*V_)     // 8192 floats per segment
#define WS_STRIDE 514       // u64 (float2) per s-slice: 512 + 2 pad -> bank offset 4s
#define NBLOCKS 296         // 2 per SM on 148 SMs

// Thread = (row, s). Warp = 4 rows x 8 s. W (premultiplied by coef) in padded
// SMEM, broadcast-read conflict-free; x + accumulators in registers.
// Scheduling fences after each u-quad stop ptxas from hoisting itself into
// register spills (R4/R5 failure mode: 2.6GB of local traffic).
__global__ __launch_bounds__(256, 2)
void idxlin_kernel(const float* __restrict__ W,     // (C, S*U*V)
                   const float* __restrict__ X,     // (Z, S*U)
                   const int*   __restrict__ counts,
                   const float* __restrict__ coef,
                   float* __restrict__ out,         // (Z, S*V)
                   int Z)
{
    __shared__ __align__(16) unsigned long long w_sh[S_ * WS_STRIDE]; // 32.9 KB
    __shared__ int segStart[C_ + 1];

    const int tid = threadIdx.x;
    if (tid == 0) {
        int a = 0; segStart[0] = 0;
        #pragma unroll
        for (int c = 0; c < C_; ++c) { a += counts[c]; segStart[c + 1] = a; }
    }
    __syncthreads();

    const int lane = tid & 31;
    const int wid  = tid >> 5;
    const int s    = lane & 7;   // 8 s per warp -> W-LDS banks tile fully
    const int r4   = lane >> 3;  // 4 rows per warp (broadcast groups)

    const int rpb = (Z + NBLOCKS - 1) / NBLOCKS;
    const int lo  = blockIdx.x * rpb;
    const int hi  = min(lo + rpb, Z);
    if (lo >= Z) return;   // uniform per block

    int seg = 0;
    while (seg < C_ - 1 && segStart[seg + 1] <= lo) seg++;

    int cur = lo;
    while (cur < hi) {
        const int segTop = (seg < C_ - 1) ? segStart[seg + 1] : Z;
        const int e = min(segTop, hi);

        // ---- stage premultiplied W[seg] into padded SMEM (coalesced) ----
        __syncthreads();   // previous readers done with w_sh
        {
            const float4* wg = reinterpret_cast<const float4*>(W + (size_t)seg * WSEG);
            #pragma unroll
            for (int k = 0; k < WSEG / 4 / 256; ++k) {      // 8 iters
                const int idx4 = tid + 256 * k;
                float4 w = wg[idx4];
                const int ss  = idx4 >> 8;     // 256 float4 per s-slice
                const int rem = idx4 & 255;
                const float c0 = coef[ss];
                w.x *= c0; w.y *= c0; w.z *= c0; w.w *= c0;
                *reinterpret_cast<float4*>(&w_sh[ss * WS_STRIDE + rem * 2]) = w;
            }
        }
        __syncthreads();

        const unsigned long long* wbase = &w_sh[s * WS_STRIDE];

        // ---- barrier-free row loop ----
        for (int r = cur + wid * 4 + r4; r < e; r += 32) {
            const float4* xg = reinterpret_cast<const float4*>(
                X + (size_t)r * SU + s * U_);
            // Batch all x loads up front: MLP=8 on the global fetch.
            float4 x0 = xg[0], x1 = xg[1], x2 = xg[2], x3 = xg[3];
            float4 x4 = xg[4], x5 = xg[5], x6 = xg[6], x7 = xg[7];

            unsigned long long A0=0,A1=0,A2=0,A3=0,A4=0,A5=0,A6=0,A7=0,
                               A8=0,A9=0,A10=0,A11=0,A12=0,A13=0,A14=0,A15=0;

#define FMA2(acc, xx, ww) \
    asm("fma.rn.f32x2 %0, %1, %2, %0;" : "+l"(acc) : "l"(xx), "l"(ww));
#define DO_U(xs, u) {                                                          \
    unsigned long long xx;                                                     \
    asm("mov.b64 %0, {%1, %1};" : "=l"(xx) : "f"(xs));                         \
    const ulonglong2* wr = reinterpret_cast<const ulonglong2*>(                \
        wbase + (u) * (V_ / 2));                                               \
    ulonglong2 ww;                                                             \
    ww = wr[0]; FMA2(A0,  xx, ww.x) FMA2(A1,  xx, ww.y)                        \
    ww = wr[1]; FMA2(A2,  xx, ww.x) FMA2(A3,  xx, ww.y)                        \
    ww = wr[2]; FMA2(A4,  xx, ww.x) FMA2(A5,  xx, ww.y)                        \
    ww = wr[3]; FMA2(A6,  xx, ww.x) FMA2(A7,  xx, ww.y)                        \
    ww = wr[4]; FMA2(A8,  xx, ww.x) FMA2(A9,  xx, ww.y)                        \
    ww = wr[5]; FMA2(A10, xx, ww.x) FMA2(A11, xx, ww.y)                        \
    ww = wr[6]; FMA2(A12, xx, ww.x) FMA2(A13, xx, ww.y)                        \
    ww = wr[7]; FMA2(A14, xx, ww.x) FMA2(A15, xx, ww.y)                        \
    }
// Scheduling fence: keeps ptxas's hoisting window to one u-quad so it cannot
// inflate register pressure past the cap and spill the accumulators.
#define FENCE() asm volatile("" ::: "memory");
#define DO_QUAD(xq, ub) DO_U((xq).x, ub) DO_U((xq).y, (ub)+1) \
                        DO_U((xq).z, (ub)+2) DO_U((xq).w, (ub)+3) FENCE()

            DO_QUAD(x0,  0) DO_QUAD(x1,  4) DO_QUAD(x2,  8) DO_QUAD(x3, 12)
            DO_QUAD(x4, 16) DO_QUAD(x5, 20) DO_QUAD(x6, 24) DO_QUAD(x7, 28)
#undef DO_QUAD
#undef FENCE
#undef DO_U
#undef FMA2

            float4* og = reinterpret_cast<float4*>(out + (size_t)r * SV + s * V_);
            float2 pa, pb;
#define STORE4(k, Aa, Ab) \
    pa = *reinterpret_cast<float2*>(&Aa); pb = *reinterpret_cast<float2*>(&Ab); \
    og[k] = make_float4(pa.x, pa.y, pb.x, pb.y);
            STORE4(0, A0,  A1)  STORE4(1, A2,  A3)
            STORE4(2, A4,  A5)  STORE4(3, A6,  A7)
            STORE4(4, A8,  A9)  STORE4(5, A10, A11)
            STORE4(6, A12, A13) STORE4(7, A14, A15)
#undef STORE4
        }

        cur = e;
        seg++;
        if (seg >= C_ && cur < hi) break;  // safety if counts undersum
    }
}

extern "C" void kernel_launch(void* const* d_in, const int* in_sizes, int n_in,
                              void* d_out, int out_size) {
    const float* W      = (const float*)d_in[0];   // input1 (C, S*U*V)
    const float* X      = (const float*)d_in[1];   // input2 (Z, S*U)
    const int*   counts = (const int*)d_in[2];
    const float* coef   = (const float*)d_in[3];
    float* out = (float*)d_out;

    int Z = in_sizes[1] / SU;
    idxlin_kernel<<<NBLOCKS, 256>>>(W, X, counts, coef, out, Z);
}